// round 7
// baseline (speedup 1.0000x reference)
#include <cuda_runtime.h>

#define BATCH 16
#define HH 512
#define WW 512
#define HWSZ (HH * WW)

// ---- scratch (no allocations allowed; zero-initialized at module load) ----
__device__ float g_colsum[BATCH][WW];   // de_h summed over H, per column (only [0..510] used)
__device__ float g_rowsum[BATCH][HH];   // de_v summed over W, per row    (only [0..510] used)
__device__ int   g_dec[BATCH][4];       // kh, blocked_h, kv, blocked_v

__device__ __forceinline__ float lum1(const float* p) {
    return 0.299f * p[0] + 0.587f * p[HWSZ] + 0.114f * p[2 * HWSZ];
}
__device__ __forceinline__ float2 lum2(float2 c0, float2 c1, float2 c2) {
    float2 l;
    l.x = 0.299f * c0.x + 0.587f * c1.x + 0.114f * c2.x;
    l.y = 0.299f * c0.y + 0.587f * c1.y + 0.114f * c2.y;
    return l;
}
// clipped excess: max(|t0-t1| - |r0-r1|, 0)
__device__ __forceinline__ float dexc(float t0, float t1, float r0, float r1) {
    return fmaxf(fabsf(t0 - t1) - fabsf(r0 - r1), 0.0f);
}

// -------------------------------------------------------------------------
// Kernel 1: software-pipelined streaming reduction.
// Block = 8 warps stacked vertically: 64 rows x 64 cols. Warp w owns rows
// r0 = rg*64 + w*8 .. +7, cols strip*64 + lane*2 (float2 per lane).
// 2-stage pipeline: next row's 6 loads issue right after current row's lum
// is formed, so loads stay in flight during shuffle/dexc work.
// Vertical boundary pair (r0+7, r0+8) resolved via smem: each warp parks
// its row-0 luminance, one __syncthreads, warp w reads warp w+1's entry.
// Only warp 7 (block bottom edge) reloads one row -> 1/64 redundancy.
// grid: BATCH * 8 rowgroups * 8 strips = 1024 blocks of 256 threads.
// -------------------------------------------------------------------------
__global__ __launch_bounds__(256) void jb_accum_kernel(
    const float* __restrict__ ref, const float* __restrict__ tgt)
{
    const int wid   = threadIdx.x >> 5;
    const int lane  = threadIdx.x & 31;
    const int blk   = blockIdx.x;
    const int b     = blk >> 6;          // 64 blocks per batch
    const int rem   = blk & 63;
    const int rg    = rem >> 3;          // row group (64 rows each)
    const int strip = rem & 7;           // 64-col strip
    const int r0    = rg * 64 + wid * 8;
    const int c0    = strip * 64 + lane * 2;

    __shared__ float2 s_lr0[8][32];      // row-0 luminance per warp (ref)
    __shared__ float2 s_lt0[8][32];      // row-0 luminance per warp (tgt)

    const float* rp = ref + (size_t)b * 3 * HWSZ + (size_t)r0 * WW + c0;
    const float* tp = tgt + (size_t)b * 3 * HWSZ + (size_t)r0 * WW + c0;

    const bool bnd_load = (lane == 31) && (strip < 7);   // col c0+2 in next strip
    const bool bnd_skip = (lane == 31) && (strip == 7);  // col 511: no right neighbor

    // stage-0 loads: row r0
    float2 a0 = *reinterpret_cast<const float2*>(rp);
    float2 a1 = *reinterpret_cast<const float2*>(rp + HWSZ);
    float2 a2 = *reinterpret_cast<const float2*>(rp + 2 * HWSZ);
    float2 t0 = *reinterpret_cast<const float2*>(tp);
    float2 t1 = *reinterpret_cast<const float2*>(tp + HWSZ);
    float2 t2 = *reinterpret_cast<const float2*>(tp + 2 * HWSZ);

    float2 cacc = make_float2(0.f, 0.f);
    float2 plr, plt;

    #pragma unroll
    for (int i = 0; i < 8; ++i) {
        float2 lr = lum2(a0, a1, a2);
        float2 lt = lum2(t0, t1, t2);
        const float* rpc = rp;           // current-row pointers (for lane-31 lum1)
        const float* tpc = tp;

        // issue NEXT row's loads now; they fly during the compute below
        if (i < 7) {
            rp += WW; tp += WW;
            a0 = *reinterpret_cast<const float2*>(rp);
            a1 = *reinterpret_cast<const float2*>(rp + HWSZ);
            a2 = *reinterpret_cast<const float2*>(rp + 2 * HWSZ);
            t0 = *reinterpret_cast<const float2*>(tp);
            t1 = *reinterpret_cast<const float2*>(tp + HWSZ);
            t2 = *reinterpret_cast<const float2*>(tp + 2 * HWSZ);
        }

        if (i == 0) { s_lr0[wid][lane] = lr; s_lt0[wid][lane] = lt; }

        // ---- horizontal ----
        float nr = __shfl_down_sync(0xffffffffu, lr.x, 1);
        float nt = __shfl_down_sync(0xffffffffu, lt.x, 1);
        if (bnd_load) {                  // boundary luminance (col c0+2)
            nr = lum1(rpc + 2);
            nt = lum1(tpc + 2);
        }
        cacc.x += dexc(lt.x, lt.y, lr.x, lr.y);
        if (!bnd_skip)
            cacc.y += dexc(lt.y, nt, lr.y, nr);

        // ---- vertical pair (r-1, r) ----
        if (i > 0) {
            float dv = dexc(plt.x, lt.x, plr.x, lr.x)
                     + dexc(plt.y, lt.y, plr.y, lr.y);
            #pragma unroll
            for (int off = 16; off > 0; off >>= 1)
                dv += __shfl_down_sync(0xffffffffu, dv, off);
            if (lane == 0)
                atomicAdd(&g_rowsum[b][r0 + i - 1], dv);
        }
        plr = lr; plt = lt;
    }

    __syncthreads();

    // ---- boundary vertical pair (r0+7, r0+8) ----
    if ((wid < 7) || (rg < 7)) {
        float2 nlr, nlt;
        if (wid < 7) {
            nlr = s_lr0[wid + 1][lane];
            nlt = s_lt0[wid + 1][lane];
        } else {                         // block bottom edge: reload one row
            const float* rn = rp + WW;   // rp points at row r0+7
            const float* tn = tp + WW;
            nlr.x = lum1(rn);     nlr.y = lum1(rn + 1);
            nlt.x = lum1(tn);     nlt.y = lum1(tn + 1);
        }
        float dv = dexc(plt.x, nlt.x, plr.x, nlr.x)
                 + dexc(plt.y, nlt.y, plr.y, nlr.y);
        #pragma unroll
        for (int off = 16; off > 0; off >>= 1)
            dv += __shfl_down_sync(0xffffffffu, dv, off);
        if (lane == 0)
            atomicAdd(&g_rowsum[b][r0 + 7], dv);
    }

    atomicAdd(&g_colsum[b][c0 + 0], cacc.x);
    atomicAdd(&g_colsum[b][c0 + 1], cacc.y);
}

// -------------------------------------------------------------------------
// Kernel 2: per-batch phase decision. Also ZEROES the accumulators it
// consumed, so graph replays start clean.
// one block per batch, 128 threads: 0..63 cols (h), 64..127 rows (v).
// -------------------------------------------------------------------------
__global__ void jb_decide_kernel() {
    const int b = blockIdx.x;
    const int t = threadIdx.x;

    __shared__ float ph[2][8];
    if (t < 16) ph[t >> 3][t & 7] = 0.0f;
    __syncthreads();

    const int grp = t >> 6;        // 0 = h (cols), 1 = v (rows)
    const int i0  = t & 63;
    float* src = grp ? g_rowsum[b] : g_colsum[b];

    float acc = 0.0f;
    for (int i = i0; i < 512; i += 64) {
        if (i < 511) acc += src[i] * (1.0f / 512.0f);
        src[i] = 0.0f;             // reset for next graph replay
    }
    atomicAdd(&ph[grp][i0 & 7], acc);
    __syncthreads();

    if (t < 2) {
        float total = 0.0f;
        #pragma unroll
        for (int k = 0; k < 8; ++k) total += ph[t][k];
        float best_r = -1.0f;
        int   best_k = 0;
        #pragma unroll
        for (int k = 0; k < 8; ++k) {
            float cnt   = (k < 7) ? 64.0f : 63.0f;   // 511 lines: phases 0..6 have 64
            float a_k   = ph[t][k] / cnt;
            float bg    = (total - ph[t][k]) / (511.0f - cnt);
            float ratio = a_k / (bg + 1e-8f);
            if (ratio > best_r) { best_r = ratio; best_k = k; }  // first-max
        }
        int blocked = best_r > (1.0f / 0.35f);
        g_dec[b][t * 2 + 0] = best_k;
        g_dec[b][t * 2 + 1] = blocked;
    }
}

// -------------------------------------------------------------------------
// Kernel 3: paint the output mask. 32 floats (8 x STG.128) per thread.
// -------------------------------------------------------------------------
__global__ __launch_bounds__(256) void jb_write_kernel(float* __restrict__ out) {
    const int idx = blockIdx.x * 256 + threadIdx.x;   // B*H*W/32 = 131072 threads
    const int c32 = idx & 15;            // 16 chunks of 32 cols per row
    const int r   = (idx >> 4) & (HH - 1);
    const int b   = idx >> 13;

    const int kh = g_dec[b][0], bh = g_dec[b][1];
    const int kv = g_dec[b][2], bv = g_dec[b][3];

    const bool vrow = bv && ((r & 7) == kv) && (r < HH - 1);
    const bool tail = (c32 == 15);       // chunk containing col 511

    float4 o[8];
    float* op = reinterpret_cast<float*>(o);
    #pragma unroll
    for (int j = 0; j < 32; ++j) {
        bool vcol = bh && ((j & 7) == kh) && !(tail && j == 31);
        op[j] = (vrow || vcol) ? 1.0f : 0.0f;
    }
    float4* dst = reinterpret_cast<float4*>(out + (size_t)idx * 32);
    #pragma unroll
    for (int j = 0; j < 8; ++j) dst[j] = o[j];
}

// -------------------------------------------------------------------------
extern "C" void kernel_launch(void* const* d_in, const int* in_sizes, int n_in,
                              void* d_out, int out_size)
{
    const float* ref = (const float*)d_in[0];
    const float* tgt = (const float*)d_in[1];
    float* out = (float*)d_out;

    // 16 batches * 8 rowgroups * 8 strips = 1024 blocks of 8 warps
    jb_accum_kernel<<<1024, 256>>>(ref, tgt);

    jb_decide_kernel<<<BATCH, 128>>>();

    jb_write_kernel<<<BATCH * HH * WW / 32 / 256, 256>>>(out);
}